// round 1
// baseline (speedup 1.0000x reference)
#include <cuda_runtime.h>
#include <cuda_bf16.h>
#include <math.h>

#define NN 100000
#define NE 1600000
#define EPS 1e-5f

// ---------------- device scratch (no allocs allowed) ----------------
__device__ int   g_cnt[NN];
__device__ int   g_off[NN + 1];
__device__ int   g_cur[NN];
__device__ float g_inv[NN];
__device__ int   g_col[NE];
__device__ float g_agg[(size_t)NN * 128];
__device__ float g_pre[(size_t)NN * 128];
__device__ float g_h[(size_t)NN * 128];
__device__ float g_sum[128];
__device__ float g_ssq[128];
__device__ float g_scale[128];
__device__ float g_shift[128];

// ---------------- CSR build ----------------
__global__ void zero_cnt_kernel() {
    int i = blockIdx.x * blockDim.x + threadIdx.x;
    if (i < NN) g_cnt[i] = 0;
}

__global__ void hist_kernel(const int* __restrict__ dst) {
    int e = blockIdx.x * blockDim.x + threadIdx.x;
    if (e < NE) atomicAdd(&g_cnt[dst[e]], 1);
}

__global__ void scan_kernel() {
    __shared__ int s[1024];
    const int t = threadIdx.x;
    const int chunk = (NN + 1023) / 1024;
    int start = t * chunk;
    int end = start + chunk; if (end > NN) end = NN;
    if (start > NN) start = NN;
    int sum = 0;
    for (int i = start; i < end; i++) sum += g_cnt[i];
    s[t] = sum;
    __syncthreads();
    for (int off = 1; off < 1024; off <<= 1) {
        int v = (t >= off) ? s[t - off] : 0;
        __syncthreads();
        s[t] += v;
        __syncthreads();
    }
    int excl = (t == 0) ? 0 : s[t - 1];
    for (int i = start; i < end; i++) {
        int c = g_cnt[i];
        g_off[i] = excl;
        g_cur[i] = excl;
        g_inv[i] = 1.0f / fmaxf((float)c, 1.0f);
        excl += c;
    }
    if (t == 1023) g_off[NN] = s[1023];
}

__global__ void fill_kernel(const int* __restrict__ src, const int* __restrict__ dst) {
    int e = blockIdx.x * blockDim.x + threadIdx.x;
    if (e < NE) {
        int d = dst[e];
        int p = atomicAdd(&g_cur[d], 1);
        g_col[p] = src[e];
    }
}

// ---------------- mean aggregation: warp per node, float4 lanes ----------------
__global__ void agg_kernel(const float* __restrict__ hin) {
    int w = (blockIdx.x * blockDim.x + threadIdx.x) >> 5;
    if (w >= NN) return;
    int lane = threadIdx.x & 31;
    const float4* h4 = (const float4*)hin;
    float4 acc = make_float4(0.f, 0.f, 0.f, 0.f);
    int e0 = g_off[w], e1 = g_off[w + 1];
    for (int j = e0; j < e1; j++) {
        int s = g_col[j];
        float4 v = __ldg(&h4[(size_t)s * 32 + lane]);
        acc.x += v.x; acc.y += v.y; acc.z += v.z; acc.w += v.w;
    }
    float iv = g_inv[w];
    ((float4*)g_agg)[(size_t)w * 32 + lane] =
        make_float4(acc.x * iv, acc.y * iv, acc.z * iv, acc.w * iv);
}

// ---------------- fused dual-GEMM: pre = agg@Wl^T + h@Wr^T + bias ----------------
// K = 256 (128 agg | 128 h). BM=128, BN=COUT, BK=16, 256 threads, thread tile 8xTN.
template <int COUT>
__global__ __launch_bounds__(256, 1) void gemm_kernel(
    const float* __restrict__ Ah,
    const float* __restrict__ Wl, const float* __restrict__ Wr,
    const float* __restrict__ bias)
{
    constexpr int BM = 128, BK = 16, TN = COUT / 16, WTS = COUT + 4;
    extern __shared__ float smem[];
    float* WT = smem;                 // [256][WTS] transposed weights
    float* As = smem + 256 * WTS;     // [2][BK][BM]

    const int tid = threadIdx.x;

    // load transposed weights (coalesced global read, 4-way-conflict smem store, once per block)
    for (int i = tid; i < COUT * 128; i += 256) {
        int c = i >> 7, k = i & 127;
        WT[k * WTS + c]         = Wl[i];
        WT[(k + 128) * WTS + c] = Wr[i];
    }

    const int tx = tid & 15, ty = tid >> 4;
    const int row0 = blockIdx.x * BM;
    const int ar = tid >> 1;          // row within tile 0..127
    const int ah = (tid & 1) * 8;     // k offset 0 or 8
    const int grow = row0 + ar;
    const bool rowok = grow < NN;

    float acc[8][TN];
#pragma unroll
    for (int i = 0; i < 8; i++)
#pragma unroll
        for (int j = 0; j < TN; j++) acc[i][j] = 0.f;

    float4 ra0, ra1;
    // stage 0 (k0 = 0 -> agg part)
    if (rowok) {
        const float4* p = (const float4*)(g_agg + (size_t)grow * 128 + ah);
        ra0 = p[0]; ra1 = p[1];
    } else {
        ra0 = make_float4(0.f, 0.f, 0.f, 0.f); ra1 = ra0;
    }
    {
        float* d = As;
        d[(ah + 0) * BM + ar] = ra0.x; d[(ah + 1) * BM + ar] = ra0.y;
        d[(ah + 2) * BM + ar] = ra0.z; d[(ah + 3) * BM + ar] = ra0.w;
        d[(ah + 4) * BM + ar] = ra1.x; d[(ah + 5) * BM + ar] = ra1.y;
        d[(ah + 6) * BM + ar] = ra1.z; d[(ah + 7) * BM + ar] = ra1.w;
    }
    __syncthreads();

    for (int kt = 0; kt < 16; kt++) {
        if (kt < 15) {
            int k0 = (kt + 1) * BK;
            const float* sp = (k0 < 128) ? g_agg : Ah;
            int kk = (k0 & 127) + ah;
            if (rowok) {
                const float4* p = (const float4*)(sp + (size_t)grow * 128 + kk);
                ra0 = p[0]; ra1 = p[1];
            } else {
                ra0 = make_float4(0.f, 0.f, 0.f, 0.f); ra1 = ra0;
            }
        }
        const float* Ab = As + (kt & 1) * BK * BM;
        const float* Wb = WT + kt * BK * WTS;
#pragma unroll
        for (int k = 0; k < BK; k++) {
            float4 a0 = *(const float4*)(Ab + k * BM + ty * 8);
            float4 a1 = *(const float4*)(Ab + k * BM + ty * 8 + 4);
            float a[8] = {a0.x, a0.y, a0.z, a0.w, a1.x, a1.y, a1.z, a1.w};
            float b[TN];
#pragma unroll
            for (int j = 0; j < TN; j += 4) {
                float4 bv = *(const float4*)(Wb + k * WTS + tx * TN + j);
                b[j] = bv.x; b[j + 1] = bv.y; b[j + 2] = bv.z; b[j + 3] = bv.w;
            }
#pragma unroll
            for (int i = 0; i < 8; i++)
#pragma unroll
                for (int j = 0; j < TN; j++)
                    acc[i][j] = fmaf(a[i], b[j], acc[i][j]);
        }
        __syncthreads();
        if (kt < 15) {
            float* d = As + ((kt + 1) & 1) * BK * BM;
            d[(ah + 0) * BM + ar] = ra0.x; d[(ah + 1) * BM + ar] = ra0.y;
            d[(ah + 2) * BM + ar] = ra0.z; d[(ah + 3) * BM + ar] = ra0.w;
            d[(ah + 4) * BM + ar] = ra1.x; d[(ah + 5) * BM + ar] = ra1.y;
            d[(ah + 6) * BM + ar] = ra1.z; d[(ah + 7) * BM + ar] = ra1.w;
            __syncthreads();
        }
    }

    float bv[TN];
#pragma unroll
    for (int j = 0; j < TN; j++) bv[j] = bias[tx * TN + j];
#pragma unroll
    for (int i = 0; i < 8; i++) {
        int r = row0 + ty * 8 + i;
        if (r < NN) {
#pragma unroll
            for (int j = 0; j < TN; j += 4) {
                float4 o = make_float4(acc[i][j] + bv[j], acc[i][j + 1] + bv[j + 1],
                                       acc[i][j + 2] + bv[j + 2], acc[i][j + 3] + bv[j + 3]);
                *(float4*)(g_pre + (size_t)r * COUT + tx * TN + j) = o;
            }
        }
    }
}

// ---------------- BatchNorm stats + fold ----------------
__global__ void zero_bn_kernel() {
    int t = threadIdx.x;
    if (t < 128) { g_sum[t] = 0.f; g_ssq[t] = 0.f; }
}

__global__ void bnstats_kernel(int C) {
    int c = threadIdx.x;                 // blockDim.x == C
    float s = 0.f, q = 0.f;
    for (int r = blockIdx.x; r < NN; r += gridDim.x) {
        float v = g_pre[(size_t)r * C + c];
        s += v; q += v * v;
    }
    atomicAdd(&g_sum[c], s);
    atomicAdd(&g_ssq[c], q);
}

__global__ void bnfinal_kernel(const float* __restrict__ gamma,
                               const float* __restrict__ beta, int C) {
    int c = threadIdx.x;
    if (c < C) {
        float m = g_sum[c] * (1.0f / (float)NN);
        float v = g_ssq[c] * (1.0f / (float)NN) - m * m;
        float s = gamma[c] * rsqrtf(v + EPS);
        g_scale[c] = s;
        g_shift[c] = beta[c] - m * s;
    }
}

template <bool RELU, int C>
__global__ void norm_kernel(float* __restrict__ outp) {
    const int total4 = NN * C / 4;
    const float4* p4 = (const float4*)g_pre;
    float4* o4 = (float4*)outp;
    for (int i = blockIdx.x * blockDim.x + threadIdx.x; i < total4;
         i += gridDim.x * blockDim.x) {
        int c = (i * 4) & (C - 1);
        float4 v = p4[i];
        float4 sc = *(const float4*)(g_scale + c);
        float4 sh = *(const float4*)(g_shift + c);
        float4 r;
        r.x = fmaf(v.x, sc.x, sh.x); r.y = fmaf(v.y, sc.y, sh.y);
        r.z = fmaf(v.z, sc.z, sh.z); r.w = fmaf(v.w, sc.w, sh.w);
        if (RELU) {
            r.x = fmaxf(r.x, 0.f); r.y = fmaxf(r.y, 0.f);
            r.z = fmaxf(r.z, 0.f); r.w = fmaxf(r.w, 0.f);
        }
        o4[i] = r;
    }
}

// ---------------- launch ----------------
extern "C" void kernel_launch(void* const* d_in, const int* in_sizes, int n_in,
                              void* d_out, int out_size) {
    const float* x   = (const float*)d_in[0];
    const int*   ei  = (const int*)d_in[1];
    const int*   esrc = ei;
    const int*   edst = ei + NE;
    const float* Wl0 = (const float*)d_in[2];
    const float* bl0 = (const float*)d_in[3];
    const float* Wr0 = (const float*)d_in[4];
    const float* ga0 = (const float*)d_in[5];
    const float* be0 = (const float*)d_in[6];
    const float* Wl1 = (const float*)d_in[7];
    const float* bl1 = (const float*)d_in[8];
    const float* Wr1 = (const float*)d_in[9];
    const float* ga1 = (const float*)d_in[10];
    const float* be1 = (const float*)d_in[11];
    const float* Wl2 = (const float*)d_in[12];
    const float* bl2 = (const float*)d_in[13];
    const float* Wr2 = (const float*)d_in[14];
    const float* ga2 = (const float*)d_in[15];
    const float* be2 = (const float*)d_in[16];
    float* out = (float*)d_out;

    const int smem128 = (256 * (128 + 4) + 2 * 16 * 128) * sizeof(float);
    const int smem64  = (256 * (64 + 4)  + 2 * 16 * 128) * sizeof(float);
    cudaFuncSetAttribute(gemm_kernel<128>, cudaFuncAttributeMaxDynamicSharedMemorySize, smem128);
    cudaFuncSetAttribute(gemm_kernel<64>,  cudaFuncAttributeMaxDynamicSharedMemorySize, smem64);

    // hidden buffer pointer (device symbol referenced inside kernels; agg/norm need it as arg)
    // We pass the __device__ symbol address via a small trick: kernels that read the hidden
    // state take a pointer; obtain it once per call.
    float* hbuf = nullptr;
    cudaGetSymbolAddress((void**)&hbuf, g_h);

    // ---- CSR build ----
    zero_cnt_kernel<<<(NN + 255) / 256, 256>>>();
    hist_kernel<<<NE / 256, 256>>>(edst);
    scan_kernel<<<1, 1024>>>();
    fill_kernel<<<NE / 256, 256>>>(esrc, edst);

    const int aggBlocks = NN / 8;            // 8 warps per 256-thread block
    const int gemmBlocks = (NN + 127) / 128; // 782

    // ---- layer 0 ----
    agg_kernel<<<aggBlocks, 256>>>(x);
    gemm_kernel<128><<<gemmBlocks, 256, smem128>>>(x, Wl0, Wr0, bl0);
    zero_bn_kernel<<<1, 128>>>();
    bnstats_kernel<<<512, 128>>>(128);
    bnfinal_kernel<<<1, 128>>>(ga0, be0, 128);
    norm_kernel<true, 128><<<2048, 256>>>(hbuf);

    // ---- layer 1 ----
    agg_kernel<<<aggBlocks, 256>>>(hbuf);
    gemm_kernel<128><<<gemmBlocks, 256, smem128>>>(hbuf, Wl1, Wr1, bl1);
    zero_bn_kernel<<<1, 128>>>();
    bnstats_kernel<<<512, 128>>>(128);
    bnfinal_kernel<<<1, 128>>>(ga1, be1, 128);
    norm_kernel<true, 128><<<2048, 256>>>(hbuf);

    // ---- layer 2 ----
    agg_kernel<<<aggBlocks, 256>>>(hbuf);
    gemm_kernel<64><<<gemmBlocks, 256, smem64>>>(hbuf, Wl2, Wr2, bl2);
    zero_bn_kernel<<<1, 128>>>();
    bnstats_kernel<<<512, 64>>>(64);
    bnfinal_kernel<<<1, 64>>>(ga2, be2, 64);
    norm_kernel<false, 64><<<2048, 256>>>(out);
}

// round 3
// speedup vs baseline: 1.4343x; 1.4343x over previous
#include <cuda_runtime.h>
#include <cuda_bf16.h>
#include <cstdint>
#include <math.h>

#define NN 100000
#define NE 1600000
#define EPS 1e-5f

// ================= device scratch =================
__device__ int   g_cnt[NN];
__device__ int   g_off[NN + 1];
__device__ int   g_cur[NN];
__device__ float g_inv[NN];
__device__ int   g_col[NE];
__device__ float g_agg[(size_t)NN * 128];
__device__ float g_pre[(size_t)NN * 128];
__device__ float g_h[(size_t)NN * 128];
__device__ float g_sum[128];
__device__ float g_ssq[128];
__device__ float g_scale[128];
__device__ float g_shift[128];

__device__ __forceinline__ uint32_t tf32u(float x) {
    uint32_t y; asm("cvt.rna.tf32.f32 %0, %1;" : "=r"(y) : "f"(x)); return y;
}

// ================= CSR build =================
__global__ void zero_cnt_kernel() {
    int i = blockIdx.x * blockDim.x + threadIdx.x;
    if (i < NN) g_cnt[i] = 0;
}
__global__ void hist_kernel(const int* __restrict__ dst) {
    int e = blockIdx.x * blockDim.x + threadIdx.x;
    if (e < NE) atomicAdd(&g_cnt[dst[e]], 1);
}
__global__ void scan_kernel() {
    __shared__ int s[1024];
    const int t = threadIdx.x;
    const int chunk = (NN + 1023) / 1024;
    int start = t * chunk;
    int end = start + chunk; if (end > NN) end = NN;
    if (start > NN) start = NN;
    int sum = 0;
    for (int i = start; i < end; i++) sum += g_cnt[i];
    s[t] = sum;
    __syncthreads();
    for (int off = 1; off < 1024; off <<= 1) {
        int v = (t >= off) ? s[t - off] : 0;
        __syncthreads();
        s[t] += v;
        __syncthreads();
    }
    int excl = (t == 0) ? 0 : s[t - 1];
    for (int i = start; i < end; i++) {
        int c = g_cnt[i];
        g_off[i] = excl;
        g_cur[i] = excl;
        g_inv[i] = 1.0f / fmaxf((float)c, 1.0f);
        excl += c;
    }
    if (t == 1023) g_off[NN] = s[1023];
}
__global__ void fill_kernel(const int* __restrict__ src, const int* __restrict__ dst) {
    int e = blockIdx.x * blockDim.x + threadIdx.x;
    if (e < NE) {
        int d = dst[e];
        int p = atomicAdd(&g_cur[d], 1);
        g_col[p] = src[e];
    }
}

// ================= mean aggregation (warp/node, float4 lanes) =================
__global__ void agg_kernel(const float* __restrict__ hin) {
    int w = (blockIdx.x * blockDim.x + threadIdx.x) >> 5;
    if (w >= NN) return;
    int lane = threadIdx.x & 31;
    const float4* h4 = (const float4*)hin;
    float4 acc = make_float4(0.f, 0.f, 0.f, 0.f);
    int e0 = g_off[w], e1 = g_off[w + 1];
    for (int j = e0; j < e1; j++) {
        int s = g_col[j];
        float4 v = __ldg(&h4[(size_t)s * 32 + lane]);
        acc.x += v.x; acc.y += v.y; acc.z += v.z; acc.w += v.w;
    }
    float iv = g_inv[w];
    ((float4*)g_agg)[(size_t)w * 32 + lane] =
        make_float4(acc.x * iv, acc.y * iv, acc.z * iv, acc.w * iv);
}

// ================= tf32 mma.sync dual-GEMM =================
// pre[r, 0:COUT] = agg[r,:]@Wl^T + h[r,:]@Wr^T + bias.  K = 256 (agg | h).
// Block: 256 thr (8 warps), BM=128, BN=COUT. Warp tile 32 x (COUT/2).
// Smem: A staged [2][128][ASTR=36] (chunked K=32), B resident [COUT][BSTR=260].
// Both layouts give conflict-free fragment LDS (bank = 4*group + tig).
template <int COUT>
__global__ __launch_bounds__(256, 1) void gemm_mma_kernel(
    const float* __restrict__ Aagg, const float* __restrict__ Ah,
    const float* __restrict__ Wl, const float* __restrict__ Wr,
    const float* __restrict__ bias, float* __restrict__ outp)
{
    constexpr int ASTR = 36, BSTR = 260;
    constexpr int NT = COUT / 16;              // n-tiles per warp (8 or 4)
    extern __shared__ float smem[];
    float* Bs = smem;                          // [COUT][BSTR]
    float* As = smem + COUT * BSTR;            // [2][128][ASTR]

    const int tid = threadIdx.x, wid = tid >> 5, lane = tid & 31;
    const int g = lane >> 2, tig = lane & 3;
    const int row0 = blockIdx.x * 128;
    const int m0 = (wid >> 1) * 32;
    const int n0 = (wid & 1) * (COUT / 2);

    // ---- fill B (tf32-rounded), coalesced float4 both sides ----
    for (int i = tid; i < COUT * 64; i += 256) {
        int n = i >> 6, k4 = i & 63;
        int k = k4 * 4;
        const float* W = (k < 128) ? Wl : Wr;
        float4 v = *(const float4*)(W + n * 128 + (k & 127));
        uint4 u = make_uint4(tf32u(v.x), tf32u(v.y), tf32u(v.z), tf32u(v.w));
        *(uint4*)(Bs + n * BSTR + k) = u;
    }

    // ---- stage A chunk 0 ----
    {
        for (int t = 0; t < 4; t++) {
            int i = tid + t * 256;
            int row = i >> 3, k4 = i & 7;
            int grow = row0 + row;
            float4 v = make_float4(0.f, 0.f, 0.f, 0.f);
            if (grow < NN) v = *(const float4*)(Aagg + (size_t)grow * 128 + k4 * 4);
            uint4 u = make_uint4(tf32u(v.x), tf32u(v.y), tf32u(v.z), tf32u(v.w));
            *(uint4*)(As + row * ASTR + k4 * 4) = u;
        }
    }
    __syncthreads();

    float acc[2][NT][4];
#pragma unroll
    for (int mt = 0; mt < 2; mt++)
#pragma unroll
        for (int nt = 0; nt < NT; nt++)
#pragma unroll
            for (int j = 0; j < 4; j++) acc[mt][nt][j] = 0.f;

    for (int c = 0; c < 8; c++) {
        float4 r[4];
        if (c < 7) {
            int cn = c + 1;
            const float* src = (cn < 4) ? Aagg : Ah;
            int koff = (cn & 3) * 32;
#pragma unroll
            for (int t = 0; t < 4; t++) {
                int i = tid + t * 256;
                int row = i >> 3, k4 = i & 7;
                int grow = row0 + row;
                r[t] = make_float4(0.f, 0.f, 0.f, 0.f);
                if (grow < NN) r[t] = *(const float4*)(src + (size_t)grow * 128 + koff + k4 * 4);
            }
        }
        const float* Ab = As + (c & 1) * 128 * ASTR;
        const float* Bb = Bs + c * 32;
#pragma unroll
        for (int kk = 0; kk < 32; kk += 8) {
            uint32_t a[2][4], b[NT][2];
#pragma unroll
            for (int mt = 0; mt < 2; mt++) {
                const float* ap = Ab + (m0 + mt * 16 + g) * ASTR + kk + tig;
                a[mt][0] = __float_as_uint(ap[0]);
                a[mt][1] = __float_as_uint(ap[8 * ASTR]);
                a[mt][2] = __float_as_uint(ap[4]);
                a[mt][3] = __float_as_uint(ap[8 * ASTR + 4]);
            }
#pragma unroll
            for (int nt = 0; nt < NT; nt++) {
                const float* bp = Bb + (n0 + nt * 8 + g) * BSTR + kk + tig;
                b[nt][0] = __float_as_uint(bp[0]);
                b[nt][1] = __float_as_uint(bp[4]);
            }
#pragma unroll
            for (int mt = 0; mt < 2; mt++)
#pragma unroll
                for (int nt = 0; nt < NT; nt++)
                    asm volatile(
                        "mma.sync.aligned.m16n8k8.row.col.f32.tf32.tf32.f32 "
                        "{%0,%1,%2,%3}, {%4,%5,%6,%7}, {%8,%9}, {%0,%1,%2,%3};"
                        : "+f"(acc[mt][nt][0]), "+f"(acc[mt][nt][1]),
                          "+f"(acc[mt][nt][2]), "+f"(acc[mt][nt][3])
                        : "r"(a[mt][0]), "r"(a[mt][1]), "r"(a[mt][2]), "r"(a[mt][3]),
                          "r"(b[nt][0]), "r"(b[nt][1]));
        }
        __syncthreads();
        if (c < 7) {
            float* d = As + ((c + 1) & 1) * 128 * ASTR;
#pragma unroll
            for (int t = 0; t < 4; t++) {
                int i = tid + t * 256;
                int row = i >> 3, k4 = i & 7;
                uint4 u = make_uint4(tf32u(r[t].x), tf32u(r[t].y), tf32u(r[t].z), tf32u(r[t].w));
                *(uint4*)(d + row * ASTR + k4 * 4) = u;
            }
            __syncthreads();
        }
    }

    // ---- epilogue: bias + store ----
#pragma unroll
    for (int mt = 0; mt < 2; mt++) {
        int rA = row0 + m0 + mt * 16 + g;
        int rB = rA + 8;
#pragma unroll
        for (int nt = 0; nt < NT; nt++) {
            int col = n0 + nt * 8 + tig * 2;
            float b0 = bias[col], b1 = bias[col + 1];
            if (rA < NN)
                *(float2*)(outp + (size_t)rA * COUT + col) =
                    make_float2(acc[mt][nt][0] + b0, acc[mt][nt][1] + b1);
            if (rB < NN)
                *(float2*)(outp + (size_t)rB * COUT + col) =
                    make_float2(acc[mt][nt][2] + b0, acc[mt][nt][3] + b1);
        }
    }
}

// ================= BatchNorm =================
__global__ void zero_bn_kernel() {
    int t = threadIdx.x;
    if (t < 128) { g_sum[t] = 0.f; g_ssq[t] = 0.f; }
}
__global__ void bnstats_kernel(int C) {
    int c = threadIdx.x;
    float s = 0.f, q = 0.f;
    for (int r = blockIdx.x; r < NN; r += gridDim.x) {
        float v = g_pre[(size_t)r * C + c];
        s += v; q += v * v;
    }
    atomicAdd(&g_sum[c], s);
    atomicAdd(&g_ssq[c], q);
}
__global__ void bnfinal_kernel(const float* __restrict__ gamma,
                               const float* __restrict__ beta, int C) {
    int c = threadIdx.x;
    if (c < C) {
        float m = g_sum[c] * (1.0f / (float)NN);
        float v = g_ssq[c] * (1.0f / (float)NN) - m * m;
        float s = gamma[c] * rsqrtf(v + EPS);
        g_scale[c] = s;
        g_shift[c] = beta[c] - m * s;
    }
}
template <bool RELU, int C>
__global__ void norm_kernel(float* __restrict__ outp) {
    const int total4 = NN * C / 4;
    const float4* p4 = (const float4*)g_pre;
    float4* o4 = (float4*)outp;
    for (int i = blockIdx.x * blockDim.x + threadIdx.x; i < total4;
         i += gridDim.x * blockDim.x) {
        int c = (i * 4) & (C - 1);
        float4 v = p4[i];
        float4 sc = *(const float4*)(g_scale + c);
        float4 sh = *(const float4*)(g_shift + c);
        float4 r;
        r.x = fmaf(v.x, sc.x, sh.x); r.y = fmaf(v.y, sc.y, sh.y);
        r.z = fmaf(v.z, sc.z, sh.z); r.w = fmaf(v.w, sc.w, sh.w);
        if (RELU) {
            r.x = fmaxf(r.x, 0.f); r.y = fmaxf(r.y, 0.f);
            r.z = fmaxf(r.z, 0.f); r.w = fmaxf(r.w, 0.f);
        }
        o4[i] = r;
    }
}

// ================= launch =================
extern "C" void kernel_launch(void* const* d_in, const int* in_sizes, int n_in,
                              void* d_out, int out_size) {
    const float* x    = (const float*)d_in[0];
    const int*   ei   = (const int*)d_in[1];
    const int*   esrc = ei;
    const int*   edst = ei + NE;
    const float* Wl0 = (const float*)d_in[2];
    const float* bl0 = (const float*)d_in[3];
    const float* Wr0 = (const float*)d_in[4];
    const float* ga0 = (const float*)d_in[5];
    const float* be0 = (const float*)d_in[6];
    const float* Wl1 = (const float*)d_in[7];
    const float* bl1 = (const float*)d_in[8];
    const float* Wr1 = (const float*)d_in[9];
    const float* ga1 = (const float*)d_in[10];
    const float* be1 = (const float*)d_in[11];
    const float* Wl2 = (const float*)d_in[12];
    const float* bl2 = (const float*)d_in[13];
    const float* Wr2 = (const float*)d_in[14];
    const float* ga2 = (const float*)d_in[15];
    const float* be2 = (const float*)d_in[16];
    float* out = (float*)d_out;

    const int smem128 = (128 * 260 + 2 * 128 * 36) * sizeof(float);  // 169984
    const int smem64  = (64 * 260 + 2 * 128 * 36) * sizeof(float);   // 103424
    cudaFuncSetAttribute(gemm_mma_kernel<128>, cudaFuncAttributeMaxDynamicSharedMemorySize, smem128);
    cudaFuncSetAttribute(gemm_mma_kernel<64>,  cudaFuncAttributeMaxDynamicSharedMemorySize, smem64);

    float *hbuf = nullptr, *aggp = nullptr, *prep = nullptr;
    cudaGetSymbolAddress((void**)&hbuf, g_h);
    cudaGetSymbolAddress((void**)&aggp, g_agg);
    cudaGetSymbolAddress((void**)&prep, g_pre);

    // ---- CSR build ----
    zero_cnt_kernel<<<(NN + 255) / 256, 256>>>();
    hist_kernel<<<NE / 256, 256>>>(edst);
    scan_kernel<<<1, 1024>>>();
    fill_kernel<<<NE / 256, 256>>>(esrc, edst);

    const int aggBlocks = NN / 8;
    const int gemmBlocks = (NN + 127) / 128;

    // ---- layer 0 ----
    agg_kernel<<<aggBlocks, 256>>>(x);
    gemm_mma_kernel<128><<<gemmBlocks, 256, smem128>>>(aggp, x, Wl0, Wr0, bl0, prep);
    zero_bn_kernel<<<1, 128>>>();
    bnstats_kernel<<<512, 128>>>(128);
    bnfinal_kernel<<<1, 128>>>(ga0, be0, 128);
    norm_kernel<true, 128><<<2048, 256>>>(hbuf);

    // ---- layer 1 ----
    agg_kernel<<<aggBlocks, 256>>>(hbuf);
    gemm_mma_kernel<128><<<gemmBlocks, 256, smem128>>>(aggp, hbuf, Wl1, Wr1, bl1, prep);
    zero_bn_kernel<<<1, 128>>>();
    bnstats_kernel<<<512, 128>>>(128);
    bnfinal_kernel<<<1, 128>>>(ga1, be1, 128);
    norm_kernel<true, 128><<<2048, 256>>>(hbuf);

    // ---- layer 2 ----
    agg_kernel<<<aggBlocks, 256>>>(hbuf);
    gemm_mma_kernel<64><<<gemmBlocks, 256, smem64>>>(aggp, hbuf, Wl2, Wr2, bl2, prep);
    zero_bn_kernel<<<1, 128>>>();
    bnstats_kernel<<<512, 64>>>(64);
    bnfinal_kernel<<<1, 64>>>(ga2, be2, 64);
    norm_kernel<false, 64><<<2048, 256>>>(out);
}